// round 4
// baseline (speedup 1.0000x reference)
#include <cuda_runtime.h>

// Problem constants (fixed by the dataset's setup_inputs)
#define L_Q        16
#define D_MODEL    1024
#define H_HEADS    16
#define HD         64
#define BS_TOK     16
#define NB_BLOCKS  1024
#define START_POS  16368
#define T_TOTAL    16384
#define SCALE_F    0.125f   // 1/sqrt(64)

// Attention tiling
#define NC       32          // number of KV chunks (split-KV)
#define CHUNK    512         // tokens per chunk
#define TB       128         // tokens per smem tile
#define NTILES   (CHUNK/TB)

#define ATTN_SMEM_FLOATS (TB*65 + TB*64 + 16*TB + 16*64 + 48)
#define ATTN_SMEM_BYTES  (ATTN_SMEM_FLOATS * 4)

// ---------------- device scratch (no allocations allowed) ----------------
__device__ float g_qkv[L_Q * 3 * D_MODEL];            // [16][3072]
__device__ float g_part[H_HEADS * NC * L_Q * HD];     // per-chunk partial O
__device__ float g_m[H_HEADS * NC * L_Q];             // per-chunk running max
__device__ float g_s[H_HEADS * NC * L_Q];             // per-chunk running sumexp
__device__ float g_ao[L_Q * D_MODEL];                 // attention output [16][1024]

// block_ids may arrive as int32 (JAX x64-disabled) or int64. Sniff on device:
// viewed as int32, an int64 array of small non-negative ids has 0 at every odd
// index (little-endian high words); int32 arange-like content has ids[1]!=0.
__device__ __forceinline__ int load_block_id(const void* bi, int blk_idx, int is64) {
    int v;
    if (is64) v = (int)((const long long*)bi)[blk_idx];
    else      v = ((const int*)bi)[blk_idx];
    return v & (NB_BLOCKS - 1);   // memory-safety clamp (no-op for valid ids)
}

__device__ __forceinline__ int sniff_is64(const void* bi) {
    const int* b32 = (const int*)bi;
    return (b32[1] == 0 && b32[3] == 0 && b32[5] == 0 && b32[7] == 0) ? 1 : 0;
}

// ---------------- init: bias-seed qkv and d_out ----------------
__global__ void init_kernel(const float* __restrict__ b_attn,
                            const float* __restrict__ b_proj,
                            float* __restrict__ out) {
    int idx = blockIdx.x * blockDim.x + threadIdx.x;
    if (idx < L_Q * 3 * D_MODEL) g_qkv[idx] = b_attn[idx % (3 * D_MODEL)];
    if (idx < L_Q * D_MODEL)     out[idx]   = b_proj[idx & (D_MODEL - 1)];
}

// ---------------- QKV GEMM: qkv += x @ W_attn (split-K atomics) ----------------
// grid (24, 8) = (j-tiles of 128, i-chunks of 128), 128 threads
__global__ void gemm_qkv(const float* __restrict__ x, const float* __restrict__ W) {
    __shared__ float xs[L_Q][128];
    const int tid = threadIdx.x;
    const int i0 = blockIdx.y * 128;
    for (int idx = tid; idx < L_Q * 128; idx += 128) {
        int l = idx >> 7, ii = idx & 127;
        xs[l][ii] = x[l * D_MODEL + i0 + ii];
    }
    __syncthreads();
    const int j = blockIdx.x * 128 + tid;
    float acc[L_Q] = {};
    #pragma unroll 4
    for (int ii = 0; ii < 128; ii++) {
        float w = W[(long)(i0 + ii) * (3 * D_MODEL) + j];
        #pragma unroll
        for (int l = 0; l < L_Q; l++) acc[l] = fmaf(xs[l][ii], w, acc[l]);
    }
    #pragma unroll
    for (int l = 0; l < L_Q; l++) atomicAdd(&g_qkv[l * (3 * D_MODEL) + j], acc[l]);
}

// ---------------- attention partial (split-KV, online softmax) ----------------
// grid (NC, H), 128 threads, dynamic smem
__global__ void attn_kernel(const float* __restrict__ k_pool,
                            const float* __restrict__ v_pool,
                            const void*  __restrict__ block_ids) {
    extern __shared__ float smem[];
    float* Ks   = smem;                 // [TB][65]  (pad 65: stride-65 scalar LDS conflict-free)
    float* Vs   = Ks + TB * 65;         // [TB][64]
    float* Ps   = Vs + TB * 64;         // [16][TB]  scores -> probabilities
    float* Qs   = Ps + 16 * TB;         // [16][64]  pre-scaled q
    float* sm_m = Qs + 16 * 64;         // [16]
    float* sm_l = sm_m + 16;            // [16]
    float* sm_c = sm_l + 16;            // [16]

    const int h     = blockIdx.y;
    const int cidx  = blockIdx.x;
    const int cbase = cidx * CHUNK;
    const int tid   = threadIdx.x;
    const int is64  = sniff_is64(block_ids);

    for (int idx = tid; idx < 16 * 64; idx += 128) {
        int l = idx >> 6, j = idx & 63;
        Qs[idx] = g_qkv[l * (3 * D_MODEL) + h * HD + j] * SCALE_F;
    }
    if (tid < 16) { sm_m[tid] = -1e30f; sm_l[tid] = 0.f; }

    // role decompositions
    const int qkw = tid >> 5;        // QK: query-group (4 queries), lanes = tokens
    const int tg  = tid & 31;
    const int th  = tid >> 6;        // PV: token half
    const int rr  = tid & 63;
    const int lg  = rr >> 4;         // PV: query-group
    const int jg  = rr & 15;         // PV: d-group (4 cols)
    const int sq  = tid >> 3;        // softmax: query
    const int sub = tid & 7;         // softmax: 8 lanes per query (within one warp)

    float o[4][4] = {};
    __syncthreads();

    for (int tile = 0; tile < NTILES; tile++) {
        const int t0 = cbase + tile * TB;

        // ---- load K/V tile (coalesced float4, paged gather; new tokens from g_qkv) ----
        for (int idx = tid; idx < TB * 16; idx += 128) {
            int tt = idx >> 4, f = (idx & 15) << 2;
            int t = t0 + tt;
            const float *ks, *vs;
            if (t < START_POS) {
                int blk = load_block_id(block_ids, t >> 4, is64);
                long long off = ((long long)blk * BS_TOK + (t & (BS_TOK - 1)))
                                * (long long)(H_HEADS * HD) + (long long)h * HD;
                ks = k_pool + off;
                vs = v_pool + off;
            } else {
                int l = t - START_POS;
                ks = g_qkv + l * (3 * D_MODEL) + D_MODEL     + h * HD;
                vs = g_qkv + l * (3 * D_MODEL) + 2 * D_MODEL + h * HD;
            }
            float4 kv = *(const float4*)(ks + f);
            float4 vv = *(const float4*)(vs + f);
            float* kd = Ks + tt * 65 + f;
            kd[0] = kv.x; kd[1] = kv.y; kd[2] = kv.z; kd[3] = kv.w;
            *(float4*)(Vs + tt * 64 + f) = vv;
        }
        __syncthreads();

        // ---- QK: thread computes 4 tokens x 4 queries (16 accs) ----
        {
            float acc[4][4] = {};
            #pragma unroll 4
            for (int j = 0; j < 64; j++) {
                float kk[4], qq[4];
                #pragma unroll
                for (int ti = 0; ti < 4; ti++) kk[ti] = Ks[(tg + 32 * ti) * 65 + j];
                #pragma unroll
                for (int li = 0; li < 4; li++) qq[li] = Qs[(qkw * 4 + li) * 64 + j];
                #pragma unroll
                for (int ti = 0; ti < 4; ti++)
                    #pragma unroll
                    for (int li = 0; li < 4; li++)
                        acc[ti][li] = fmaf(kk[ti], qq[li], acc[ti][li]);
            }
            #pragma unroll
            for (int ti = 0; ti < 4; ti++) {
                int t = t0 + tg + 32 * ti;
                #pragma unroll
                for (int li = 0; li < 4; li++) {
                    int l = qkw * 4 + li;
                    float s = acc[ti][li];
                    if (t > START_POS + l) s = -1e30f;   // causal mask (only last block hits)
                    Ps[l * TB + tg + 32 * ti] = s;
                }
            }
        }
        __syncthreads();

        // ---- online softmax: 8 lanes per query (lane groups within one warp) ----
        {
            float oldm = sm_m[sq];
            float vals[16];
            float tmax = -1e30f;
            #pragma unroll
            for (int k = 0; k < 16; k++) {
                float v = Ps[sq * TB + sub + 8 * k];
                vals[k] = v;
                tmax = fmaxf(tmax, v);
            }
            tmax = fmaxf(tmax, __shfl_xor_sync(0xffffffffu, tmax, 1));
            tmax = fmaxf(tmax, __shfl_xor_sync(0xffffffffu, tmax, 2));
            tmax = fmaxf(tmax, __shfl_xor_sync(0xffffffffu, tmax, 4));
            float newm = fmaxf(oldm, tmax);
            float lsum = 0.f;
            #pragma unroll
            for (int k = 0; k < 16; k++) {
                float p = __expf(vals[k] - newm);
                Ps[sq * TB + sub + 8 * k] = p;
                lsum += p;
            }
            lsum += __shfl_xor_sync(0xffffffffu, lsum, 1);
            lsum += __shfl_xor_sync(0xffffffffu, lsum, 2);
            lsum += __shfl_xor_sync(0xffffffffu, lsum, 4);
            if (sub == 0) {
                float corr = __expf(oldm - newm);
                sm_c[sq] = corr;
                sm_m[sq] = newm;
                sm_l[sq] = sm_l[sq] * corr + lsum;
            }
        }
        __syncthreads();

        // ---- PV: thread accumulates 4 queries x 4 cols over its 64-token half ----
        {
            float corr[4];
            #pragma unroll
            for (int i = 0; i < 4; i++) corr[i] = sm_c[lg * 4 + i];
            #pragma unroll
            for (int i = 0; i < 4; i++)
                #pragma unroll
                for (int j = 0; j < 4; j++) o[i][j] *= corr[i];

            #pragma unroll 4
            for (int t = 0; t < 64; t++) {
                int tt = th * 64 + t;
                float pp[4];
                #pragma unroll
                for (int i = 0; i < 4; i++) pp[i] = Ps[(lg * 4 + i) * TB + tt];
                float4 v = *(const float4*)(Vs + tt * 64 + (jg << 2));
                #pragma unroll
                for (int i = 0; i < 4; i++) {
                    o[i][0] = fmaf(pp[i], v.x, o[i][0]);
                    o[i][1] = fmaf(pp[i], v.y, o[i][1]);
                    o[i][2] = fmaf(pp[i], v.z, o[i][2]);
                    o[i][3] = fmaf(pp[i], v.w, o[i][3]);
                }
            }
        }
        __syncthreads();
    }

    // ---- reduce the two token-halves and write partials ----
    float* red = Ps;  // reuse (>= 1024 floats)
    if (th == 1) {
        #pragma unroll
        for (int i = 0; i < 4; i++)
            #pragma unroll
            for (int j = 0; j < 4; j++) red[rr * 16 + i * 4 + j] = o[i][j];
    }
    __syncthreads();
    if (th == 0) {
        const int pbase = (h * NC + cidx) * L_Q;
        #pragma unroll
        for (int i = 0; i < 4; i++) {
            int l = lg * 4 + i;
            #pragma unroll
            for (int j = 0; j < 4; j++) {
                float val = o[i][j] + red[rr * 16 + i * 4 + j];
                g_part[(pbase + l) * HD + (jg << 2) + j] = val;
            }
        }
    }
    if (tid < 16) {
        int pidx = (h * NC + cidx) * L_Q + tid;
        g_m[pidx] = sm_m[tid];
        g_s[pidx] = sm_l[tid];
    }
}

// ---------------- combine split-KV partials ----------------
// grid (H), 256 threads
__global__ void combine_kernel() {
    __shared__ float w_s[NC][16];
    __shared__ float S_s[16];
    const int h = blockIdx.x;
    const int tid = threadIdx.x;
    if (tid < 16) {
        int l = tid;
        float M = -1e30f;
        for (int c = 0; c < NC; c++) M = fmaxf(M, g_m[(h * NC + c) * L_Q + l]);
        float S = 0.f;
        for (int c = 0; c < NC; c++) {
            float w = __expf(g_m[(h * NC + c) * L_Q + l] - M);
            w_s[c][l] = w;
            S += g_s[(h * NC + c) * L_Q + l] * w;
        }
        S_s[l] = S;
    }
    __syncthreads();
    for (int idx = tid; idx < L_Q * HD; idx += blockDim.x) {
        int l = idx >> 6, j = idx & 63;
        float acc = 0.f;
        #pragma unroll 4
        for (int c = 0; c < NC; c++)
            acc += g_part[((h * NC + c) * L_Q + l) * HD + j] * w_s[c][l];
        g_ao[l * D_MODEL + h * HD + j] = acc / S_s[l];
    }
}

// ---------------- output projection: out += g_ao @ W_proj ----------------
// grid (8, 8), 128 threads
__global__ void gemm_proj(const float* __restrict__ W, float* __restrict__ out) {
    __shared__ float as[L_Q][128];
    const int tid = threadIdx.x;
    const int i0 = blockIdx.y * 128;
    for (int idx = tid; idx < L_Q * 128; idx += 128) {
        int l = idx >> 7, ii = idx & 127;
        as[l][ii] = g_ao[l * D_MODEL + i0 + ii];
    }
    __syncthreads();
    const int j = blockIdx.x * 128 + tid;
    float acc[L_Q] = {};
    #pragma unroll 4
    for (int ii = 0; ii < 128; ii++) {
        float w = W[(long)(i0 + ii) * D_MODEL + j];
        #pragma unroll
        for (int l = 0; l < L_Q; l++) acc[l] = fmaf(as[l][ii], w, acc[l]);
    }
    #pragma unroll
    for (int l = 0; l < L_Q; l++) atomicAdd(&out[l * D_MODEL + j], acc[l]);
}

// ---------------- launch ----------------
extern "C" void kernel_launch(void* const* d_in, const int* in_sizes, int n_in,
                              void* d_out, int out_size) {
    const float* x       = (const float*)d_in[0];
    const float* k_pool  = (const float*)d_in[1];
    const float* v_pool  = (const float*)d_in[2];
    const float* W_attn  = (const float*)d_in[3];
    const float* b_attn  = (const float*)d_in[4];
    const float* W_proj  = (const float*)d_in[5];
    const float* b_proj  = (const float*)d_in[6];
    const void*  blk_ids = (const void*)d_in[7];
    float* out = (float*)d_out;

    static int attr_set = 0;
    if (!attr_set) {
        cudaFuncSetAttribute(attn_kernel, cudaFuncAttributeMaxDynamicSharedMemorySize,
                             ATTN_SMEM_BYTES);
        attr_set = 1;
    }

    init_kernel<<<(L_Q * 3 * D_MODEL + 255) / 256, 256>>>(b_attn, b_proj, out);
    gemm_qkv<<<dim3(24, 8), 128>>>(x, W_attn);
    attn_kernel<<<dim3(NC, H_HEADS), 128, ATTN_SMEM_BYTES>>>(k_pool, v_pool, blk_ids);
    combine_kernel<<<H_HEADS, 256>>>();
    gemm_proj<<<dim3(8, 8), 128>>>(W_proj, out);
}